// round 4
// baseline (speedup 1.0000x reference)
#include <cuda_runtime.h>
#include <cuda_bf16.h>
#include <math.h>
#include <float.h>

// Shapes (fixed): B=4, NP=4096, D_FEAT=8, N=16, DM=16, DO=8, NM=64, PNM=64
// moments K = 2*DM = 32
#define BIGF 99999999.0f

// ---------------- scratch (__device__ globals) ----------------------------
__device__ float g_n2[4 * 4096];            // squared norms
__device__ int   g_idx[4 * 4096 * 16];      // knn indices, ascending-distance order
__device__ float g_zpart[4 * 4096 * 64];    // per-(b,n) z partial sums
__device__ float g_zm[4 * 8];               // z @ Wmz + bmz
__device__ float g_zv[4 * 64];              // z @ Wvz + bvz

// ---------------- prep: norms (mul + serial rn adds, no FMA) --------------
__global__ __launch_bounds__(256) void prep_kernel(const float* __restrict__ x)
{
    int i = blockIdx.x * 256 + threadIdx.x;   // 0..16383
    if (i < 16384) {
        float4 a = *(const float4*)(x + i * 8);
        float4 b = *(const float4*)(x + i * 8 + 4);
        float s = __fmul_rn(a.x, a.x);
        s = __fadd_rn(s, __fmul_rn(a.y, a.y));
        s = __fadd_rn(s, __fmul_rn(a.z, a.z));
        s = __fadd_rn(s, __fmul_rn(a.w, a.w));
        s = __fadd_rn(s, __fmul_rn(b.x, b.x));
        s = __fadd_rn(s, __fmul_rn(b.y, b.y));
        s = __fadd_rn(s, __fmul_rn(b.z, b.z));
        s = __fadd_rn(s, __fmul_rn(b.w, b.w));
        g_n2[i] = s;
    }
}

// ---------------- z-mixing biases -----------------------------------------
__global__ void zmix_kernel(const float* __restrict__ z,
                            const float* __restrict__ Wmz, const float* __restrict__ bmz,
                            const float* __restrict__ Wvz, const float* __restrict__ bvz)
{
    int t = threadIdx.x;
    if (t < 256) {                        // zv: 4 batches x 64
        int b = t >> 6, j = t & 63;
        float s = bvz[j];
        #pragma unroll 8
        for (int p = 0; p < 64; p++) s = fmaf(z[b * 64 + p], Wvz[p * 64 + j], s);
        g_zv[t] = s;
    } else if (t < 288) {                 // zm: 4 batches x 8
        int q = t - 256;
        int b = q >> 3, j = q & 7;
        float s = bmz[j];
        #pragma unroll 8
        for (int p = 0; p < 64; p++) s = fmaf(z[b * 64 + p], Wmz[p * 8 + j], s);
        g_zm[q] = s;
    }
}

// ---------------- kNN: block per (b,i), packed-u64 tournament -------------
// Distance arithmetic mirrors XLA/cuBLAS fp32: dot = serial FMA over k
// (first term plain mul == fma into 0), n2 precomputed mul+serial-add,
// d2 = (n2i + n2j) - 2*dot with rn ops, dist = sqrt(max(d2,0)),
// 0 or diagonal -> BIG. Ties -> lower index via packed (dist,idx) compare.
__global__ __launch_bounds__(256) void knn_kernel(const float* __restrict__ x)
{
    int b = blockIdx.x >> 12;
    int i = blockIdx.x & 4095;
    int t = threadIdx.x;

    __shared__ unsigned long long redbuf[8];
    __shared__ unsigned long long best_s;

    const float* xb  = x + (b << 15);
    const float* n2b = g_n2 + (b << 12);

    float4 a0 = *(const float4*)(xb + i * 8);
    float4 a1 = *(const float4*)(xb + i * 8 + 4);
    float n2i = n2b[i];

    const unsigned long long SENT = 0xffffffffffffffffull;
    unsigned long long s0 = SENT, s1 = SENT, s2 = SENT, s3 = SENT,
                       s4 = SENT, s5 = SENT, s6 = SENT, s7 = SENT;

    #pragma unroll 4
    for (int jj = 0; jj < 16; jj++) {
        int j = (jj << 8) + t;
        float4 p0 = *(const float4*)(xb + j * 8);
        float4 p1 = *(const float4*)(xb + j * 8 + 4);
        // cublas-style serial FMA accumulation, k ascending
        float dot = __fmul_rn(a0.x, p0.x);
        dot = __fmaf_rn(a0.y, p0.y, dot);
        dot = __fmaf_rn(a0.z, p0.z, dot);
        dot = __fmaf_rn(a0.w, p0.w, dot);
        dot = __fmaf_rn(a1.x, p1.x, dot);
        dot = __fmaf_rn(a1.y, p1.y, dot);
        dot = __fmaf_rn(a1.z, p1.z, dot);
        dot = __fmaf_rn(a1.w, p1.w, dot);
        float d2 = __fsub_rn(__fadd_rn(n2i, n2b[j]), __fmul_rn(2.0f, dot));
        float dd = sqrtf(fmaxf(d2, 0.0f));
        if (dd == 0.0f || j == i) dd = BIGF;
        unsigned long long pv =
            ((unsigned long long)__float_as_uint(dd) << 32) | (unsigned)j;
        unsigned long long tv = pv, mn;
        mn = (s0 < tv) ? s0 : tv; tv = (s0 < tv) ? tv : s0; s0 = mn;
        mn = (s1 < tv) ? s1 : tv; tv = (s1 < tv) ? tv : s1; s1 = mn;
        mn = (s2 < tv) ? s2 : tv; tv = (s2 < tv) ? tv : s2; s2 = mn;
        mn = (s3 < tv) ? s3 : tv; tv = (s3 < tv) ? tv : s3; s3 = mn;
        mn = (s4 < tv) ? s4 : tv; tv = (s4 < tv) ? tv : s4; s4 = mn;
        mn = (s5 < tv) ? s5 : tv; tv = (s5 < tv) ? tv : s5; s5 = mn;
        mn = (s6 < tv) ? s6 : tv; tv = (s6 < tv) ? tv : s6; s6 = mn;
        mn = (s7 < tv) ? s7 : tv; tv = (s7 < tv) ? tv : s7; s7 = mn;
    }

    int base = (b * 4096 + i) * 16;
    for (int round = 0; round < 16; round++) {
        unsigned long long m = s0, o;
        o = __shfl_down_sync(0xffffffffu, m, 16); if (o < m) m = o;
        o = __shfl_down_sync(0xffffffffu, m, 8);  if (o < m) m = o;
        o = __shfl_down_sync(0xffffffffu, m, 4);  if (o < m) m = o;
        o = __shfl_down_sync(0xffffffffu, m, 2);  if (o < m) m = o;
        o = __shfl_down_sync(0xffffffffu, m, 1);  if (o < m) m = o;
        if ((t & 31) == 0) redbuf[t >> 5] = m;
        __syncthreads();
        if (t == 0) {
            unsigned long long mm = redbuf[0];
            #pragma unroll
            for (int w = 1; w < 8; w++) if (redbuf[w] < mm) mm = redbuf[w];
            best_s = mm;
        }
        __syncthreads();
        unsigned long long bv = best_s;
        if (t == 0) g_idx[base + round] = (int)(unsigned)(bv & 0xffffffffull);
        if (((unsigned)(bv & 0xffffffffull) & 255u) == (unsigned)t) {
            s0 = s1; s1 = s2; s2 = s3; s3 = s4;
            s4 = s5; s5 = s6; s6 = s7; s7 = SENT;
        }
    }
}

// ---------------- features + fused matmuls: block per (b,n) ---------------
// DM=16, K = 2*DM = 32 moment columns (cols 0..15 order-2, 16..31 order-3).
__global__ __launch_bounds__(128) void feat_kernel(
    const float* __restrict__ x,
    const float* __restrict__ Wm2, const float* __restrict__ bm2,
    const float* __restrict__ Wm3, const float* __restrict__ bm3,
    const float* __restrict__ Wv2, const float* __restrict__ bv2,
    const float* __restrict__ Wv3, const float* __restrict__ bv3,
    const float* __restrict__ Wmx, const float* __restrict__ bmx,
    const float* __restrict__ Wvx, const float* __restrict__ bvx,
    float* __restrict__ xout)
{
    int b = blockIdx.x >> 12;
    int n = blockIdx.x & 4095;
    int t = threadIdx.x;

    __shared__ __align__(16) float g[16][8];
    __shared__ __align__(16) float msm[15][32];
    __shared__ __align__(16) float vsm[15][32];
    __shared__ float mpart[8][8][15];   // [j][slice][r]
    __shared__ float xr[8][15];

    // gather 16 neighbor feature vectors
    {
        int s = t >> 3, d = t & 7;
        int nb = g_idx[(b * 4096 + n) * 16 + s] & 4095;
        g[s][d] = x[(size_t)(b * 4096 + nb) * 8 + d];
    }

    // feature-phase role
    int c   = t & 31;
    int mat = (t >> 5) & 1;
    int rh  = t >> 6;
    bool o3 = (c >= 16);
    int  k  = o3 ? (c - 16) : c;
    float w0, w1, w2 = 0.f, bb;
    if (!o3) {
        w0 = mat ? Wv2[k]      : Wm2[k];
        w1 = mat ? Wv2[16 + k] : Wm2[16 + k];
        bb = mat ? bv2[k]      : bm2[k];
    } else {
        w0 = mat ? Wv3[k]      : Wm3[k];
        w1 = mat ? Wv3[16 + k] : Wm3[16 + k];
        w2 = mat ? Wv3[32 + k] : Wm3[32 + k];
        bb = mat ? bv3[k]      : bm3[k];
    }
    __syncthreads();

    // r-invariant base: order2 p = g0*w0+b ; order3 p = g0*w0+g1*w1+b
    float p[8];
    #pragma unroll
    for (int d = 0; d < 8; d++) {
        float base = fmaf(g[0][d], w0, bb);
        p[d] = o3 ? fmaf(g[1][d], w1, base) : base;
    }
    float wlast = o3 ? w2 : w1;
    float* smo = mat ? &vsm[0][0] : &msm[0][0];

    int r0 = rh ? 8 : 0;
    int r1 = rh ? 15 : 8;
    for (int r = r0; r < r1; r++) {
        float ssum = 0.f;
        if (o3 && r == 14) {
            // tuple (0,2,3): g0*w0 + g2*w1 + g3*w2 + b
            #pragma unroll
            for (int d = 0; d < 8; d++) {
                float v = fmaf(g[3][d], w2,
                          fmaf(g[2][d], w1,
                          fmaf(g[0][d], w0, bb)));
                ssum += fmaxf(v, 0.f);
            }
        } else {
            int a = o3 ? (r + 2) : (r + 1);
            #pragma unroll
            for (int d = 0; d < 8; d++)
                ssum += fmaxf(fmaf(g[a][d], wlast, p[d]), 0.f);
        }
        smo[r * 32 + c] = ssum * 0.125f;   // mean over d (8)
    }
    __syncthreads();

    if (t < 64) {
        // v-matmul: output j=t, K=32, 15 tuples
        float acc[15];
        #pragma unroll
        for (int r = 0; r < 15; r++) acc[r] = 0.f;
        #pragma unroll
        for (int k4 = 0; k4 < 32; k4 += 4) {
            float q0 = Wvx[(k4 + 0) * 64 + t];
            float q1 = Wvx[(k4 + 1) * 64 + t];
            float q2 = Wvx[(k4 + 2) * 64 + t];
            float q3 = Wvx[(k4 + 3) * 64 + t];
            #pragma unroll
            for (int r = 0; r < 15; r++) {
                float4 vv = *(const float4*)&vsm[r][k4];
                acc[r] = fmaf(vv.x, q0, acc[r]);
                acc[r] = fmaf(vv.y, q1, acc[r]);
                acc[r] = fmaf(vv.z, q2, acc[r]);
                acc[r] = fmaf(vv.w, q3, acc[r]);
            }
        }
        float bias = bvx[t] + g_zv[b * 64 + t];
        float s = 0.f;
        #pragma unroll
        for (int r = 0; r < 15; r++) s += fmaxf(acc[r] + bias, 0.f);
        g_zpart[(size_t)(b * 4096 + n) * 64 + t] = s;
    } else {
        // m-matmul: 8 outputs x 8 k-slices of 4
        int q = t - 64;
        int j = q >> 3;
        int sl = q & 7;
        int k0 = sl * 4;
        float q0 = Wmx[(k0 + 0) * 8 + j];
        float q1 = Wmx[(k0 + 1) * 8 + j];
        float q2 = Wmx[(k0 + 2) * 8 + j];
        float q3 = Wmx[(k0 + 3) * 8 + j];
        #pragma unroll
        for (int r = 0; r < 15; r++) {
            float4 mv = *(const float4*)&msm[r][k0];
            float a = mv.x * q0;
            a = fmaf(mv.y, q1, a);
            a = fmaf(mv.z, q2, a);
            a = fmaf(mv.w, q3, a);
            mpart[j][sl][r] = a;
        }
    }
    __syncthreads();

    if (t < 120) {
        int j = t / 15, r = t % 15;
        float s = 0.f;
        #pragma unroll
        for (int sl = 0; sl < 8; sl++) s += mpart[j][sl][r];
        xr[j][r] = fmaxf(s + bmx[j] + g_zm[b * 8 + j], 0.f);
    }
    __syncthreads();
    if (t < 8) {
        float s = 0.f;
        #pragma unroll
        for (int r = 0; r < 15; r++) s += xr[t][r];
        xout[(size_t)b * 32768 + n * 8 + t] = s * (1.f / 15.f);
    }
}

// ---------------- z reduction ---------------------------------------------
__global__ __launch_bounds__(256) void zred_kernel(float* __restrict__ out)
{
    int b = blockIdx.x;
    int t = threadIdx.x;
    int j = t & 63, c = t >> 6;
    const float* zp = g_zpart + (size_t)b * 262144;
    float s = 0.f;
    int n0 = c * 1024;
    for (int n = n0; n < n0 + 1024; n++) s += zp[n * 64 + j];
    __shared__ float red[256];
    red[t] = s;
    __syncthreads();
    if (t < 64) {
        float v = red[t] + red[t + 64] + red[t + 128] + red[t + 192];
        out[131072 + b * 64 + t] = v * (1.f / 61440.f);
    }
}

// ---------------- launch ---------------------------------------------------
extern "C" void kernel_launch(void* const* d_in, const int* in_sizes, int n_in,
                              void* d_out, int out_size)
{
    const float* x   = (const float*)d_in[0];
    const float* z   = (const float*)d_in[1];
    const float* Wm2 = (const float*)d_in[2];
    const float* bm2 = (const float*)d_in[3];
    const float* Wm3 = (const float*)d_in[4];
    const float* bm3 = (const float*)d_in[5];
    const float* Wv2 = (const float*)d_in[6];
    const float* bv2 = (const float*)d_in[7];
    const float* Wv3 = (const float*)d_in[8];
    const float* bv3 = (const float*)d_in[9];
    const float* Wmx = (const float*)d_in[10];
    const float* bmx = (const float*)d_in[11];
    const float* Wvx = (const float*)d_in[12];
    const float* bvx = (const float*)d_in[13];
    const float* Wmz = (const float*)d_in[14];
    const float* bmz = (const float*)d_in[15];
    const float* Wvz = (const float*)d_in[16];
    const float* bvz = (const float*)d_in[17];
    float* out = (float*)d_out;

    prep_kernel<<<64, 256>>>(x);
    zmix_kernel<<<1, 288>>>(z, Wmz, bmz, Wvz, bvz);
    knn_kernel<<<16384, 256>>>(x);
    feat_kernel<<<16384, 128>>>(x,
                                Wm2, bm2, Wm3, bm3, Wv2, bv2, Wv3, bv3,
                                Wmx, bmx, Wvx, bvx, out);
    zred_kernel<<<4, 256>>>(out);
}

// round 5
// speedup vs baseline: 1.5157x; 1.5157x over previous
#include <cuda_runtime.h>
#include <cuda_bf16.h>
#include <math.h>
#include <float.h>

// Shapes (fixed): B=4, NP=4096, D_FEAT=8, N=16, DM=16, DO=8, NM=64, PNM=64
#define BIGF 99999999.0f

// ---------------- scratch (__device__ globals) ----------------------------
__device__ int   g_idx[4 * 4096 * 16];      // knn indices, ascending-distance order
__device__ float g_zpart[4 * 4096 * 64];    // per-(b,n) z partial sums
__device__ float g_zm[4 * 8];               // z @ Wmz + bmz
__device__ float g_zv[4 * 64];              // z @ Wvz + bvz

// ---------------- z-mixing biases -----------------------------------------
__global__ void zmix_kernel(const float* __restrict__ z,
                            const float* __restrict__ Wmz, const float* __restrict__ bmz,
                            const float* __restrict__ Wvz, const float* __restrict__ bvz)
{
    int t = threadIdx.x;
    if (t < 256) {                        // zv: 4 batches x 64
        int b = t >> 6, j = t & 63;
        float s = bvz[j];
        #pragma unroll 8
        for (int p = 0; p < 64; p++) s = fmaf(z[b * 64 + p], Wvz[p * 64 + j], s);
        g_zv[t] = s;
    } else if (t < 288) {                 // zm: 4 batches x 8
        int q = t - 256;
        int b = q >> 3, j = q & 7;
        float s = bmz[j];
        #pragma unroll 8
        for (int p = 0; p < 64; p++) s = fmaf(z[b * 64 + p], Wmz[p * 8 + j], s);
        g_zm[q] = s;
    }
}

// ---------------- kNN: warp-per-query, d2 selection, late sqrt ------------
// Block: 1024 threads = 32 warps = 32 queries. All 4096 points of batch b
// staged in smem (SoA float4 + n2). Per-lane f32 sorted top-8 of d2 over 128
// candidates; 18-round warp tournament -> vT = 18th-smallest d2 (margin 2
// ranks over the needed 16 covers sqrt-rounding tie collapse); rescan
// collects all d2 <= vT, sqrts only those (~18/query), exact (dist,idx)
// packed-u64 rank sort -> first 16. d2 bit-matches the reference lowering:
// dot = serial FMA, n2 = mul + serial adds (no FMA),
// d2 = (n2i + n2j) - 2*dot with rn ops. d2<=0 or diagonal -> excluded
// (reference maps those to BIG).
#define KNN_SMEM (4096*16*2 + 4096*4 + 32*32*8)   // xs0,xs1 + n2s + lists = 155648B

__global__ __launch_bounds__(1024, 1) void knn_kernel(const float* __restrict__ x)
{
    extern __shared__ char smem_raw[];
    float4* xs0 = (float4*)smem_raw;                        // [4096]
    float4* xs1 = (float4*)(smem_raw + 4096 * 16);          // [4096]
    float*  n2s = (float*) (smem_raw + 4096 * 32);          // [4096]
    unsigned long long* lists =
        (unsigned long long*)(smem_raw + 4096 * 36);        // [32][32]

    int b  = blockIdx.x >> 7;
    int i0 = (blockIdx.x & 127) << 5;
    int tid  = threadIdx.x;
    int w    = tid >> 5;
    int lane = tid & 31;

    const float* xb = x + (b << 15);

    // stage points + n2 (exact reference formula: mul + serial rn adds)
    #pragma unroll
    for (int k = 0; k < 4; k++) {
        int p = tid + (k << 10);
        float4 a = *(const float4*)(xb + p * 8);
        float4 c = *(const float4*)(xb + p * 8 + 4);
        xs0[p] = a;
        xs1[p] = c;
        float s = __fmul_rn(a.x, a.x);
        s = __fadd_rn(s, __fmul_rn(a.y, a.y));
        s = __fadd_rn(s, __fmul_rn(a.z, a.z));
        s = __fadd_rn(s, __fmul_rn(a.w, a.w));
        s = __fadd_rn(s, __fmul_rn(c.x, c.x));
        s = __fadd_rn(s, __fmul_rn(c.y, c.y));
        s = __fadd_rn(s, __fmul_rn(c.z, c.z));
        s = __fadd_rn(s, __fmul_rn(c.w, c.w));
        n2s[p] = s;
    }
    __syncthreads();

    int i = i0 + w;                    // this warp's query
    float4 a0 = xs0[i];
    float4 a1 = xs1[i];
    float n2i = n2s[i];

    // ---- main pass: per-lane sorted top-8 of d2 (values only) ----
    float s0 = FLT_MAX, s1 = FLT_MAX, s2 = FLT_MAX, s3 = FLT_MAX,
          s4 = FLT_MAX, s5 = FLT_MAX, s6 = FLT_MAX, s7 = FLT_MAX;
    {
        int j = lane;
        #pragma unroll 4
        for (int k = 0; k < 128; k++) {
            float4 p0 = xs0[j];
            float4 p1 = xs1[j];
            float dot = __fmul_rn(a0.x, p0.x);
            dot = __fmaf_rn(a0.y, p0.y, dot);
            dot = __fmaf_rn(a0.z, p0.z, dot);
            dot = __fmaf_rn(a0.w, p0.w, dot);
            dot = __fmaf_rn(a1.x, p1.x, dot);
            dot = __fmaf_rn(a1.y, p1.y, dot);
            dot = __fmaf_rn(a1.z, p1.z, dot);
            dot = __fmaf_rn(a1.w, p1.w, dot);
            float d2 = __fsub_rn(__fadd_rn(n2i, n2s[j]), __fmul_rn(2.0f, dot));
            float key = (j == i || d2 <= 0.0f) ? FLT_MAX : d2;
            float tv = key, mn;
            mn = fminf(s0, tv); tv = fmaxf(s0, tv); s0 = mn;
            mn = fminf(s1, tv); tv = fmaxf(s1, tv); s1 = mn;
            mn = fminf(s2, tv); tv = fmaxf(s2, tv); s2 = mn;
            mn = fminf(s3, tv); tv = fmaxf(s3, tv); s3 = mn;
            mn = fminf(s4, tv); tv = fmaxf(s4, tv); s4 = mn;
            mn = fminf(s5, tv); tv = fmaxf(s5, tv); s5 = mn;
            mn = fminf(s6, tv); tv = fmaxf(s6, tv); s6 = mn;
            mn = fminf(s7, tv); tv = fmaxf(s7, tv); s7 = mn;
            j += 32;
        }
    }

    // ---- warp tournament: vT = 18th smallest d2 ----
    float head = s0;
    float vT = FLT_MAX;
    #pragma unroll 1
    for (int round = 0; round < 18; round++) {
        float m = head;
        m = fminf(m, __shfl_xor_sync(0xffffffffu, m, 16));
        m = fminf(m, __shfl_xor_sync(0xffffffffu, m, 8));
        m = fminf(m, __shfl_xor_sync(0xffffffffu, m, 4));
        m = fminf(m, __shfl_xor_sync(0xffffffffu, m, 2));
        m = fminf(m, __shfl_xor_sync(0xffffffffu, m, 1));
        vT = m;
        unsigned bal = __ballot_sync(0xffffffffu, head == m);
        int leader = __ffs(bal) - 1;
        if (lane == leader) {
            s0 = s1; s1 = s2; s2 = s3; s3 = s4;
            s4 = s5; s5 = s6; s6 = s7; s7 = FLT_MAX;
            head = s0;
        }
    }

    // ---- rescan: collect all d2 <= vT, sqrt only those ----
    int cnt = 0;
    {
        unsigned lmask = (1u << lane) - 1u;
        int j = lane;
        #pragma unroll 4
        for (int k = 0; k < 128; k++) {
            float4 p0 = xs0[j];
            float4 p1 = xs1[j];
            float dot = __fmul_rn(a0.x, p0.x);
            dot = __fmaf_rn(a0.y, p0.y, dot);
            dot = __fmaf_rn(a0.z, p0.z, dot);
            dot = __fmaf_rn(a0.w, p0.w, dot);
            dot = __fmaf_rn(a1.x, p1.x, dot);
            dot = __fmaf_rn(a1.y, p1.y, dot);
            dot = __fmaf_rn(a1.z, p1.z, dot);
            dot = __fmaf_rn(a1.w, p1.w, dot);
            float d2 = __fsub_rn(__fadd_rn(n2i, n2s[j]), __fmul_rn(2.0f, dot));
            bool pred = (j != i) && (d2 > 0.0f) && (d2 <= vT);
            unsigned bal = __ballot_sync(0xffffffffu, pred);
            if (pred) {
                int slot = cnt + __popc(bal & lmask);
                if (slot < 32) {
                    float dd = sqrtf(d2);   // exact IEEE sqrt, matches reference
                    lists[(w << 5) + slot] =
                        ((unsigned long long)__float_as_uint(dd) << 32) | (unsigned)j;
                }
            }
            cnt += __popc(bal);
            j += 32;
        }
        if (cnt > 32) cnt = 32;
    }

    // ---- exact (dist, idx) rank sort of collected, write first 16 ----
    {
        unsigned long long v = (lane < cnt) ? lists[(w << 5) + lane]
                                            : 0xffffffffffffffffull;
        int rank = 0;
        #pragma unroll
        for (int m = 0; m < 32; m++) {
            unsigned long long o = __shfl_sync(0xffffffffu, v, m);
            rank += (o < v) ? 1 : 0;
        }
        if (rank < 16 && lane < cnt)
            g_idx[(b * 4096 + i) * 16 + rank] = (int)(unsigned)(v & 0xffffffffull);
    }
}

// ---------------- features + fused matmuls: block per (b,n) ---------------
// DM=16, K = 2*DM = 32 moment columns (cols 0..15 order-2, 16..31 order-3).
__global__ __launch_bounds__(128) void feat_kernel(
    const float* __restrict__ x,
    const float* __restrict__ Wm2, const float* __restrict__ bm2,
    const float* __restrict__ Wm3, const float* __restrict__ bm3,
    const float* __restrict__ Wv2, const float* __restrict__ bv2,
    const float* __restrict__ Wv3, const float* __restrict__ bv3,
    const float* __restrict__ Wmx, const float* __restrict__ bmx,
    const float* __restrict__ Wvx, const float* __restrict__ bvx,
    float* __restrict__ xout)
{
    int b = blockIdx.x >> 12;
    int n = blockIdx.x & 4095;
    int t = threadIdx.x;

    __shared__ __align__(16) float g[16][8];
    __shared__ __align__(16) float msm[15][32];
    __shared__ __align__(16) float vsm[15][32];
    __shared__ float mpart[8][8][15];   // [j][slice][r]
    __shared__ float xr[8][15];

    // gather 16 neighbor feature vectors
    {
        int s = t >> 3, d = t & 7;
        int nb = g_idx[(b * 4096 + n) * 16 + s] & 4095;
        g[s][d] = x[(size_t)(b * 4096 + nb) * 8 + d];
    }

    // feature-phase role
    int c   = t & 31;
    int mat = (t >> 5) & 1;
    int rh  = t >> 6;
    bool o3 = (c >= 16);
    int  k  = o3 ? (c - 16) : c;
    float w0, w1, w2 = 0.f, bb;
    if (!o3) {
        w0 = mat ? Wv2[k]      : Wm2[k];
        w1 = mat ? Wv2[16 + k] : Wm2[16 + k];
        bb = mat ? bv2[k]      : bm2[k];
    } else {
        w0 = mat ? Wv3[k]      : Wm3[k];
        w1 = mat ? Wv3[16 + k] : Wm3[16 + k];
        w2 = mat ? Wv3[32 + k] : Wm3[32 + k];
        bb = mat ? bv3[k]      : bm3[k];
    }
    __syncthreads();

    // r-invariant base: order2 p = g0*w0+b ; order3 p = g0*w0+g1*w1+b
    float p[8];
    #pragma unroll
    for (int d = 0; d < 8; d++) {
        float base = fmaf(g[0][d], w0, bb);
        p[d] = o3 ? fmaf(g[1][d], w1, base) : base;
    }
    float wlast = o3 ? w2 : w1;
    float* smo = mat ? &vsm[0][0] : &msm[0][0];

    int r0 = rh ? 8 : 0;
    int r1 = rh ? 15 : 8;
    for (int r = r0; r < r1; r++) {
        float ssum = 0.f;
        if (o3 && r == 14) {
            // tuple (0,2,3): g0*w0 + g2*w1 + g3*w2 + b
            #pragma unroll
            for (int d = 0; d < 8; d++) {
                float v = fmaf(g[3][d], w2,
                          fmaf(g[2][d], w1,
                          fmaf(g[0][d], w0, bb)));
                ssum += fmaxf(v, 0.f);
            }
        } else {
            int a = o3 ? (r + 2) : (r + 1);
            #pragma unroll
            for (int d = 0; d < 8; d++)
                ssum += fmaxf(fmaf(g[a][d], wlast, p[d]), 0.f);
        }
        smo[r * 32 + c] = ssum * 0.125f;   // mean over d (8)
    }
    __syncthreads();

    if (t < 64) {
        // v-matmul: output j=t, K=32, 15 tuples
        float acc[15];
        #pragma unroll
        for (int r = 0; r < 15; r++) acc[r] = 0.f;
        #pragma unroll
        for (int k4 = 0; k4 < 32; k4 += 4) {
            float q0 = Wvx[(k4 + 0) * 64 + t];
            float q1 = Wvx[(k4 + 1) * 64 + t];
            float q2 = Wvx[(k4 + 2) * 64 + t];
            float q3 = Wvx[(k4 + 3) * 64 + t];
            #pragma unroll
            for (int r = 0; r < 15; r++) {
                float4 vv = *(const float4*)&vsm[r][k4];
                acc[r] = fmaf(vv.x, q0, acc[r]);
                acc[r] = fmaf(vv.y, q1, acc[r]);
                acc[r] = fmaf(vv.z, q2, acc[r]);
                acc[r] = fmaf(vv.w, q3, acc[r]);
            }
        }
        float bias = bvx[t] + g_zv[b * 64 + t];
        float s = 0.f;
        #pragma unroll
        for (int r = 0; r < 15; r++) s += fmaxf(acc[r] + bias, 0.f);
        g_zpart[(size_t)(b * 4096 + n) * 64 + t] = s;
    } else {
        // m-matmul: 8 outputs x 8 k-slices of 4
        int q = t - 64;
        int j = q >> 3;
        int sl = q & 7;
        int k0 = sl * 4;
        float q0 = Wmx[(k0 + 0) * 8 + j];
        float q1 = Wmx[(k0 + 1) * 8 + j];
        float q2 = Wmx[(k0 + 2) * 8 + j];
        float q3 = Wmx[(k0 + 3) * 8 + j];
        #pragma unroll
        for (int r = 0; r < 15; r++) {
            float4 mv = *(const float4*)&msm[r][k0];
            float a = mv.x * q0;
            a = fmaf(mv.y, q1, a);
            a = fmaf(mv.z, q2, a);
            a = fmaf(mv.w, q3, a);
            mpart[j][sl][r] = a;
        }
    }
    __syncthreads();

    if (t < 120) {
        int j = t / 15, r = t % 15;
        float s = 0.f;
        #pragma unroll
        for (int sl = 0; sl < 8; sl++) s += mpart[j][sl][r];
        xr[j][r] = fmaxf(s + bmx[j] + g_zm[b * 8 + j], 0.f);
    }
    __syncthreads();
    if (t < 8) {
        float s = 0.f;
        #pragma unroll
        for (int r = 0; r < 15; r++) s += xr[t][r];
        xout[(size_t)b * 32768 + n * 8 + t] = s * (1.f / 15.f);
    }
}

// ---------------- z reduction ---------------------------------------------
__global__ __launch_bounds__(256) void zred_kernel(float* __restrict__ out)
{
    int b = blockIdx.x;
    int t = threadIdx.x;
    int j = t & 63, c = t >> 6;
    const float* zp = g_zpart + (size_t)b * 262144;
    float s = 0.f;
    int n0 = c * 1024;
    for (int n = n0; n < n0 + 1024; n++) s += zp[n * 64 + j];
    __shared__ float red[256];
    red[t] = s;
    __syncthreads();
    if (t < 64) {
        float v = red[t] + red[t + 64] + red[t + 128] + red[t + 192];
        out[131072 + b * 64 + t] = v * (1.f / 61440.f);
    }
}

// ---------------- launch ---------------------------------------------------
extern "C" void kernel_launch(void* const* d_in, const int* in_sizes, int n_in,
                              void* d_out, int out_size)
{
    const float* x   = (const float*)d_in[0];
    const float* z   = (const float*)d_in[1];
    const float* Wm2 = (const float*)d_in[2];
    const float* bm2 = (const float*)d_in[3];
    const float* Wm3 = (const float*)d_in[4];
    const float* bm3 = (const float*)d_in[5];
    const float* Wv2 = (const float*)d_in[6];
    const float* bv2 = (const float*)d_in[7];
    const float* Wv3 = (const float*)d_in[8];
    const float* bv3 = (const float*)d_in[9];
    const float* Wmx = (const float*)d_in[10];
    const float* bmx = (const float*)d_in[11];
    const float* Wvx = (const float*)d_in[12];
    const float* bvx = (const float*)d_in[13];
    const float* Wmz = (const float*)d_in[14];
    const float* bmz = (const float*)d_in[15];
    const float* Wvz = (const float*)d_in[16];
    const float* bvz = (const float*)d_in[17];
    float* out = (float*)d_out;

    cudaFuncSetAttribute(knn_kernel,
                         cudaFuncAttributeMaxDynamicSharedMemorySize, KNN_SMEM);

    zmix_kernel<<<1, 288>>>(z, Wmz, bmz, Wvz, bvz);
    knn_kernel<<<512, 1024, KNN_SMEM>>>(x);
    feat_kernel<<<16384, 128>>>(x,
                                Wm2, bm2, Wm3, bm3, Wv2, bv2, Wv3, bv3,
                                Wmx, bmx, Wvx, bvx, out);
    zred_kernel<<<4, 256>>>(out);
}

// round 6
// speedup vs baseline: 2.2457x; 1.4816x over previous
#include <cuda_runtime.h>
#include <cuda_bf16.h>
#include <math.h>
#include <float.h>

// Shapes (fixed): B=4, NP=4096, D_FEAT=8, N=16, DM=16, DO=8, NM=64, PNM=64
#define BIGF 99999999.0f

// ---------------- scratch (__device__ globals) ----------------------------
__device__ int   g_idx[4 * 4096 * 16];      // knn indices, ascending-distance order
__device__ float g_zpart[4 * 4096 * 64];    // per-(b,n) z partial sums
__device__ float g_zp2[4 * 64 * 64];        // stage-1 z reduction partials
__device__ float g_zm[4 * 8];               // z @ Wmz + bmz
__device__ float g_zv[4 * 64];              // z @ Wvz + bvz

// ---------------- z-mixing biases -----------------------------------------
__global__ void zmix_kernel(const float* __restrict__ z,
                            const float* __restrict__ Wmz, const float* __restrict__ bmz,
                            const float* __restrict__ Wvz, const float* __restrict__ bvz)
{
    int t = threadIdx.x;
    if (t < 256) {                        // zv: 4 batches x 64
        int b = t >> 6, j = t & 63;
        float s = bvz[j];
        #pragma unroll 8
        for (int p = 0; p < 64; p++) s = fmaf(z[b * 64 + p], Wvz[p * 64 + j], s);
        g_zv[t] = s;
    } else if (t < 288) {                 // zm: 4 batches x 8
        int q = t - 256;
        int b = q >> 3, j = q & 7;
        float s = bmz[j];
        #pragma unroll 8
        for (int p = 0; p < 64; p++) s = fmaf(z[b * 64 + p], Wmz[p * 8 + j], s);
        g_zm[q] = s;
    }
}

// ---------------- kNN: warp-per-query, single pass, packed keys -----------
// key = (d2_bits & ~0xFFF) | j : positive-float order == (d2 quantized to
// 2^-11 relative, idx) lexicographic, so plain fminf/fmaxf CE carries the
// index for free. Per-lane sorted top-8 over 128 candidates; 19-round warp
// tournament emits the 19 smallest keys (margin 3 over the needed 16 covers
// quantization-bucket collisions); survivors' d2/dist recomputed with the
// reference's exact arithmetic (serial FMA dot, n2 = mul+serial add,
// (n2i+n2j)-2*dot, sqrt) and rank-sorted by exact (dist, idx).
#define KNN_SMEM (4096*16*2 + 4096*4)   // xs0, xs1, n2s = 147456 B

__global__ __launch_bounds__(1024, 1) void knn_kernel(const float* __restrict__ x)
{
    extern __shared__ char smem_raw[];
    float4* xs0 = (float4*)smem_raw;                        // [4096]
    float4* xs1 = (float4*)(smem_raw + 4096 * 16);          // [4096]
    float*  n2s = (float*) (smem_raw + 4096 * 32);          // [4096]

    int b  = blockIdx.x >> 7;
    int i0 = (blockIdx.x & 127) << 5;
    int tid  = threadIdx.x;
    int w    = tid >> 5;
    int lane = tid & 31;

    const float* xb = x + (b << 15);

    // stage points + exact n2 (mul + serial rn adds, matches reference)
    #pragma unroll
    for (int k = 0; k < 4; k++) {
        int p = tid + (k << 10);
        float4 a = *(const float4*)(xb + p * 8);
        float4 c = *(const float4*)(xb + p * 8 + 4);
        xs0[p] = a;
        xs1[p] = c;
        float s = __fmul_rn(a.x, a.x);
        s = __fadd_rn(s, __fmul_rn(a.y, a.y));
        s = __fadd_rn(s, __fmul_rn(a.z, a.z));
        s = __fadd_rn(s, __fmul_rn(a.w, a.w));
        s = __fadd_rn(s, __fmul_rn(c.x, c.x));
        s = __fadd_rn(s, __fmul_rn(c.y, c.y));
        s = __fadd_rn(s, __fmul_rn(c.z, c.z));
        s = __fadd_rn(s, __fmul_rn(c.w, c.w));
        n2s[p] = s;
    }
    __syncthreads();

    int i = i0 + w;                    // this warp's query
    float4 a0 = xs0[i];
    float4 a1 = xs1[i];
    float n2i = n2s[i];

    // ---- single pass: per-lane sorted top-8 of packed keys ----
    float s0 = FLT_MAX, s1 = FLT_MAX, s2 = FLT_MAX, s3 = FLT_MAX,
          s4 = FLT_MAX, s5 = FLT_MAX, s6 = FLT_MAX, s7 = FLT_MAX;
    {
        int j = lane;
        #pragma unroll 4
        for (int k = 0; k < 128; k++) {
            float4 p0 = xs0[j];
            float4 p1 = xs1[j];
            // fast d2: contraction-friendly (exactness not needed here;
            // absorbed by the 2^-11 quantization margin)
            float dot = fmaf(a0.x, p0.x,
                        fmaf(a0.y, p0.y,
                        fmaf(a0.z, p0.z,
                        fmaf(a0.w, p0.w,
                        fmaf(a1.x, p1.x,
                        fmaf(a1.y, p1.y,
                        fmaf(a1.z, p1.z, a1.w * p1.w)))))));
            float d2 = fmaf(-2.0f, dot, n2i + n2s[j]);
            unsigned kb = (__float_as_uint(d2) & 0xFFFFF000u) | (unsigned)j;
            float key = (j == i || d2 <= 0.0f) ? FLT_MAX : __uint_as_float(kb);
            float tv = key, mn;
            mn = fminf(s0, tv); tv = fmaxf(s0, tv); s0 = mn;
            mn = fminf(s1, tv); tv = fmaxf(s1, tv); s1 = mn;
            mn = fminf(s2, tv); tv = fmaxf(s2, tv); s2 = mn;
            mn = fminf(s3, tv); tv = fmaxf(s3, tv); s3 = mn;
            mn = fminf(s4, tv); tv = fmaxf(s4, tv); s4 = mn;
            mn = fminf(s5, tv); tv = fmaxf(s5, tv); s5 = mn;
            mn = fminf(s6, tv); tv = fmaxf(s6, tv); s6 = mn;
            mn = fminf(s7, tv); tv = fmaxf(s7, tv); s7 = mn;
            j += 32;
        }
    }

    // ---- 19-round tournament: lane r keeps the r-th smallest key ----
    float head = s0;
    float surv = FLT_MAX;
    #pragma unroll 1
    for (int round = 0; round < 19; round++) {
        float m = head;
        m = fminf(m, __shfl_xor_sync(0xffffffffu, m, 16));
        m = fminf(m, __shfl_xor_sync(0xffffffffu, m, 8));
        m = fminf(m, __shfl_xor_sync(0xffffffffu, m, 4));
        m = fminf(m, __shfl_xor_sync(0xffffffffu, m, 2));
        m = fminf(m, __shfl_xor_sync(0xffffffffu, m, 1));
        if (round == lane) surv = m;
        unsigned bal = __ballot_sync(0xffffffffu, head == m);
        int leader = __ffs(bal) - 1;
        if (lane == leader) {
            s0 = s1; s1 = s2; s2 = s3; s3 = s4;
            s4 = s5; s5 = s6; s6 = s7; s7 = FLT_MAX;
            head = s0;
        }
    }

    // ---- exact recompute + (dist, idx) rank sort of the 19 survivors ----
    {
        bool valid = (lane < 19) && (surv != FLT_MAX);
        int j = (int)(__float_as_uint(surv) & 0xFFFu);
        unsigned long long pk = 0xffffffffffffffffull;
        if (valid) {
            float4 p0 = xs0[j];
            float4 p1 = xs1[j];
            // reference-exact: serial FMA dot, (n2i+n2j) - 2*dot, sqrt
            float dot = __fmul_rn(a0.x, p0.x);
            dot = __fmaf_rn(a0.y, p0.y, dot);
            dot = __fmaf_rn(a0.z, p0.z, dot);
            dot = __fmaf_rn(a0.w, p0.w, dot);
            dot = __fmaf_rn(a1.x, p1.x, dot);
            dot = __fmaf_rn(a1.y, p1.y, dot);
            dot = __fmaf_rn(a1.z, p1.z, dot);
            dot = __fmaf_rn(a1.w, p1.w, dot);
            float d2 = __fsub_rn(__fadd_rn(n2i, n2s[j]), __fmul_rn(2.0f, dot));
            float dd = sqrtf(fmaxf(d2, 0.0f));
            if (dd == 0.0f || j == i) dd = BIGF;
            pk = ((unsigned long long)__float_as_uint(dd) << 32) | (unsigned)j;
        }
        int rank = 0;
        #pragma unroll
        for (int m = 0; m < 32; m++) {
            unsigned long long o = __shfl_sync(0xffffffffu, pk, m);
            rank += (o < pk) ? 1 : 0;
        }
        if (valid && rank < 16)
            g_idx[(b * 4096 + i) * 16 + rank] = j;
    }
}

// ---------------- features + fused matmuls: block per (b,n) ---------------
// DM=16, K = 2*DM = 32 moment columns (cols 0..15 order-2, 16..31 order-3).
__global__ __launch_bounds__(128) void feat_kernel(
    const float* __restrict__ x,
    const float* __restrict__ Wm2, const float* __restrict__ bm2,
    const float* __restrict__ Wm3, const float* __restrict__ bm3,
    const float* __restrict__ Wv2, const float* __restrict__ bv2,
    const float* __restrict__ Wv3, const float* __restrict__ bv3,
    const float* __restrict__ Wmx, const float* __restrict__ bmx,
    const float* __restrict__ Wvx, const float* __restrict__ bvx,
    float* __restrict__ xout)
{
    int b = blockIdx.x >> 12;
    int n = blockIdx.x & 4095;
    int t = threadIdx.x;

    __shared__ __align__(16) float g[16][8];
    __shared__ __align__(16) float msm[15][32];
    __shared__ __align__(16) float vsm[15][32];
    __shared__ float mpart[8][8][15];   // [j][slice][r]
    __shared__ float xr[8][15];

    // gather 16 neighbor feature vectors
    {
        int s = t >> 3, d = t & 7;
        int nb = g_idx[(b * 4096 + n) * 16 + s] & 4095;
        g[s][d] = x[(size_t)(b * 4096 + nb) * 8 + d];
    }

    // feature-phase role
    int c   = t & 31;
    int mat = (t >> 5) & 1;
    int rh  = t >> 6;
    bool o3 = (c >= 16);
    int  k  = o3 ? (c - 16) : c;
    float w0, w1, w2 = 0.f, bb;
    if (!o3) {
        w0 = mat ? Wv2[k]      : Wm2[k];
        w1 = mat ? Wv2[16 + k] : Wm2[16 + k];
        bb = mat ? bv2[k]      : bm2[k];
    } else {
        w0 = mat ? Wv3[k]      : Wm3[k];
        w1 = mat ? Wv3[16 + k] : Wm3[16 + k];
        w2 = mat ? Wv3[32 + k] : Wm3[32 + k];
        bb = mat ? bv3[k]      : bm3[k];
    }
    __syncthreads();

    // r-invariant base: order2 p = g0*w0+b ; order3 p = g0*w0+g1*w1+b
    float p[8];
    #pragma unroll
    for (int d = 0; d < 8; d++) {
        float base = fmaf(g[0][d], w0, bb);
        p[d] = o3 ? fmaf(g[1][d], w1, base) : base;
    }
    float wlast = o3 ? w2 : w1;
    float* smo = mat ? &vsm[0][0] : &msm[0][0];

    int r0 = rh ? 8 : 0;
    int r1 = rh ? 15 : 8;
    for (int r = r0; r < r1; r++) {
        float ssum = 0.f;
        if (o3 && r == 14) {
            // tuple (0,2,3): g0*w0 + g2*w1 + g3*w2 + b
            #pragma unroll
            for (int d = 0; d < 8; d++) {
                float v = fmaf(g[3][d], w2,
                          fmaf(g[2][d], w1,
                          fmaf(g[0][d], w0, bb)));
                ssum += fmaxf(v, 0.f);
            }
        } else {
            int a = o3 ? (r + 2) : (r + 1);
            #pragma unroll
            for (int d = 0; d < 8; d++)
                ssum += fmaxf(fmaf(g[a][d], wlast, p[d]), 0.f);
        }
        smo[r * 32 + c] = ssum * 0.125f;   // mean over d (8)
    }
    __syncthreads();

    if (t < 64) {
        // v-matmul: output j=t, K=32, 15 tuples
        float acc[15];
        #pragma unroll
        for (int r = 0; r < 15; r++) acc[r] = 0.f;
        #pragma unroll
        for (int k4 = 0; k4 < 32; k4 += 4) {
            float q0 = Wvx[(k4 + 0) * 64 + t];
            float q1 = Wvx[(k4 + 1) * 64 + t];
            float q2 = Wvx[(k4 + 2) * 64 + t];
            float q3 = Wvx[(k4 + 3) * 64 + t];
            #pragma unroll
            for (int r = 0; r < 15; r++) {
                float4 vv = *(const float4*)&vsm[r][k4];
                acc[r] = fmaf(vv.x, q0, acc[r]);
                acc[r] = fmaf(vv.y, q1, acc[r]);
                acc[r] = fmaf(vv.z, q2, acc[r]);
                acc[r] = fmaf(vv.w, q3, acc[r]);
            }
        }
        float bias = bvx[t] + g_zv[b * 64 + t];
        float s = 0.f;
        #pragma unroll
        for (int r = 0; r < 15; r++) s += fmaxf(acc[r] + bias, 0.f);
        g_zpart[(size_t)(b * 4096 + n) * 64 + t] = s;
    } else {
        // m-matmul: 8 outputs x 8 k-slices of 4
        int q = t - 64;
        int j = q >> 3;
        int sl = q & 7;
        int k0 = sl * 4;
        float q0 = Wmx[(k0 + 0) * 8 + j];
        float q1 = Wmx[(k0 + 1) * 8 + j];
        float q2 = Wmx[(k0 + 2) * 8 + j];
        float q3 = Wmx[(k0 + 3) * 8 + j];
        #pragma unroll
        for (int r = 0; r < 15; r++) {
            float4 mv = *(const float4*)&msm[r][k0];
            float a = mv.x * q0;
            a = fmaf(mv.y, q1, a);
            a = fmaf(mv.z, q2, a);
            a = fmaf(mv.w, q3, a);
            mpart[j][sl][r] = a;
        }
    }
    __syncthreads();

    if (t < 120) {
        int j = t / 15, r = t % 15;
        float s = 0.f;
        #pragma unroll
        for (int sl = 0; sl < 8; sl++) s += mpart[j][sl][r];
        xr[j][r] = fmaxf(s + bmx[j] + g_zm[b * 8 + j], 0.f);
    }
    __syncthreads();
    if (t < 8) {
        float s = 0.f;
        #pragma unroll
        for (int r = 0; r < 15; r++) s += xr[t][r];
        xout[(size_t)b * 32768 + n * 8 + t] = s * (1.f / 15.f);
    }
}

// ---------------- z reduction, two-stage ----------------------------------
__global__ __launch_bounds__(256) void zred1_kernel()
{
    int b = blockIdx.x >> 6;
    int c = blockIdx.x & 63;
    int t = threadIdx.x;
    int q = t >> 6, j = t & 63;
    const float* zp = g_zpart + ((size_t)(b * 4096 + c * 64) * 64);
    float s = 0.f;
    #pragma unroll 4
    for (int k = q * 16; k < q * 16 + 16; k++) s += zp[k * 64 + j];
    __shared__ float red[256];
    red[t] = s;
    __syncthreads();
    if (t < 64)
        g_zp2[(b * 64 + c) * 64 + t] =
            red[t] + red[t + 64] + red[t + 128] + red[t + 192];
}

__global__ __launch_bounds__(64) void zred2_kernel(float* __restrict__ out)
{
    int b = blockIdx.x;
    int j = threadIdx.x;
    float s = 0.f;
    #pragma unroll 8
    for (int c = 0; c < 64; c++) s += g_zp2[(b * 64 + c) * 64 + j];
    out[131072 + b * 64 + j] = s * (1.f / 61440.f);
}

// ---------------- launch ---------------------------------------------------
extern "C" void kernel_launch(void* const* d_in, const int* in_sizes, int n_in,
                              void* d_out, int out_size)
{
    const float* x   = (const float*)d_in[0];
    const float* z   = (const float*)d_in[1];
    const float* Wm2 = (const float*)d_in[2];
    const float* bm2 = (const float*)d_in[3];
    const float* Wm3 = (const float*)d_in[4];
    const float* bm3 = (const float*)d_in[5];
    const float* Wv2 = (const float*)d_in[6];
    const float* bv2 = (const float*)d_in[7];
    const float* Wv3 = (const float*)d_in[8];
    const float* bv3 = (const float*)d_in[9];
    const float* Wmx = (const float*)d_in[10];
    const float* bmx = (const float*)d_in[11];
    const float* Wvx = (const float*)d_in[12];
    const float* bvx = (const float*)d_in[13];
    const float* Wmz = (const float*)d_in[14];
    const float* bmz = (const float*)d_in[15];
    const float* Wvz = (const float*)d_in[16];
    const float* bvz = (const float*)d_in[17];
    float* out = (float*)d_out;

    cudaFuncSetAttribute(knn_kernel,
                         cudaFuncAttributeMaxDynamicSharedMemorySize, KNN_SMEM);

    zmix_kernel<<<1, 288>>>(z, Wmz, bmz, Wvz, bvz);
    knn_kernel<<<512, 1024, KNN_SMEM>>>(x);
    feat_kernel<<<16384, 128>>>(x,
                                Wm2, bm2, Wm3, bm3, Wv2, bv2, Wv3, bv3,
                                Wmx, bmx, Wvx, bvx, out);
    zred1_kernel<<<256, 256>>>();
    zred2_kernel<<<4, 64>>>(out);
}